// round 1
// baseline (speedup 1.0000x reference)
#include <cuda_runtime.h>
#include <math.h>

#define BB 2
#define SS 2048
#define EE 1024
#define HH 16
#define DD 64

// Scratch (allocation-free rule: __device__ globals)
__device__ float g_Q[BB*HH*SS*DD];
__device__ float g_K[BB*HH*SS*DD];
__device__ float g_V[BB*HH*SS*DD];
__device__ float g_ctx[BB*SS*EE];

// ---------------- SGEMM config ----------------
#define BM 128
#define BN 128
#define BK 16
#define TM 8
#define TN 8
// 256 threads: 16x16, each owns an 8x8 microtile

// QKV projection: for z in {0,1,2}, X_z[4096,1024] @ Wqkv[:, z*1024 + n] + bias,
// scattered into [B,H,S,D] layout.
__global__ __launch_bounds__(256) void qkv_gemm(
    const float* __restrict__ q, const float* __restrict__ k, const float* __restrict__ v,
    const float* __restrict__ Wqkv, const float* __restrict__ bqkv)
{
    const int z = blockIdx.z;
    const float* A    = (z == 0) ? q : (z == 1) ? k : v;
    const float* Bm   = Wqkv + z * EE;
    const float* bias = bqkv + z * EE;
    float* out        = (z == 0) ? g_Q : (z == 1) ? g_K : g_V;
    const int lda = EE;
    const int ldb = 3 * EE;

    __shared__ float As[BK][BM];
    __shared__ float Bs[BK][BN];

    const int tid = threadIdx.x;
    const int tx = tid & 15;
    const int ty = tid >> 4;

    float acc[TM][TN];
    #pragma unroll
    for (int i = 0; i < TM; i++)
        #pragma unroll
        for (int j = 0; j < TN; j++) acc[i][j] = 0.f;

    const float* Ab = A + (size_t)(blockIdx.y * BM) * lda;
    const float* Bb = Bm + blockIdx.x * BN;

    for (int k0 = 0; k0 < EE; k0 += BK) {
        // Load A tile 128x16 (transposed into As)
        #pragma unroll
        for (int i = 0; i < 2; i++) {
            int vv = tid + i * 256;
            int r  = vv >> 2;           // 0..127
            int c  = (vv & 3) << 2;     // 0,4,8,12
            float4 a4 = *(const float4*)(Ab + (size_t)r * lda + k0 + c);
            As[c + 0][r] = a4.x; As[c + 1][r] = a4.y;
            As[c + 2][r] = a4.z; As[c + 3][r] = a4.w;
        }
        // Load B tile 16x128
        #pragma unroll
        for (int i = 0; i < 2; i++) {
            int vv = tid + i * 256;
            int r  = vv >> 5;           // 0..15
            int c  = (vv & 31) << 2;    // 0..124
            *(float4*)(&Bs[r][c]) = *(const float4*)(Bb + (size_t)(k0 + r) * ldb + c);
        }
        __syncthreads();
        #pragma unroll
        for (int kk = 0; kk < BK; kk++) {
            float ra[TM], rb[TN];
            #pragma unroll
            for (int i = 0; i < TM; i++) ra[i] = As[kk][ty * TM + i];
            #pragma unroll
            for (int j = 0; j < TN; j++) rb[j] = Bs[kk][tx * TN + j];
            #pragma unroll
            for (int i = 0; i < TM; i++)
                #pragma unroll
                for (int j = 0; j < TN; j++) acc[i][j] += ra[i] * rb[j];
        }
        __syncthreads();
    }

    const int row0 = blockIdx.y * BM + ty * TM;
    const int col0 = blockIdx.x * BN + tx * TN;
    #pragma unroll
    for (int i = 0; i < TM; i++) {
        int row = row0 + i;
        int b = row >> 11;            // /2048
        int s = row & (SS - 1);
        #pragma unroll
        for (int j = 0; j < TN; j++) {
            int col = col0 + j;
            int h = col >> 6;         // /64
            int d = col & 63;
            out[(((b * HH + h) * SS + s) * DD) + d] = acc[i][j] + bias[col];
        }
    }
}

// Output projection: g_ctx[4096,1024] @ Wout[1024,1024] + bout -> d_out
__global__ __launch_bounds__(256) void out_gemm(
    const float* __restrict__ Wout, const float* __restrict__ bout, float* __restrict__ out)
{
    const float* A = g_ctx;
    const int lda = EE;
    const int ldb = EE;

    __shared__ float As[BK][BM];
    __shared__ float Bs[BK][BN];

    const int tid = threadIdx.x;
    const int tx = tid & 15;
    const int ty = tid >> 4;

    float acc[TM][TN];
    #pragma unroll
    for (int i = 0; i < TM; i++)
        #pragma unroll
        for (int j = 0; j < TN; j++) acc[i][j] = 0.f;

    const float* Ab = A + (size_t)(blockIdx.y * BM) * lda;
    const float* Bb = Wout + blockIdx.x * BN;

    for (int k0 = 0; k0 < EE; k0 += BK) {
        #pragma unroll
        for (int i = 0; i < 2; i++) {
            int vv = tid + i * 256;
            int r  = vv >> 2;
            int c  = (vv & 3) << 2;
            float4 a4 = *(const float4*)(Ab + (size_t)r * lda + k0 + c);
            As[c + 0][r] = a4.x; As[c + 1][r] = a4.y;
            As[c + 2][r] = a4.z; As[c + 3][r] = a4.w;
        }
        #pragma unroll
        for (int i = 0; i < 2; i++) {
            int vv = tid + i * 256;
            int r  = vv >> 5;
            int c  = (vv & 31) << 2;
            *(float4*)(&Bs[r][c]) = *(const float4*)(Bb + (size_t)(k0 + r) * ldb + c);
        }
        __syncthreads();
        #pragma unroll
        for (int kk = 0; kk < BK; kk++) {
            float ra[TM], rb[TN];
            #pragma unroll
            for (int i = 0; i < TM; i++) ra[i] = As[kk][ty * TM + i];
            #pragma unroll
            for (int j = 0; j < TN; j++) rb[j] = Bs[kk][tx * TN + j];
            #pragma unroll
            for (int i = 0; i < TM; i++)
                #pragma unroll
                for (int j = 0; j < TN; j++) acc[i][j] += ra[i] * rb[j];
        }
        __syncthreads();
    }

    const int row0 = blockIdx.y * BM + ty * TM;
    const int col0 = blockIdx.x * BN + tx * TN;
    #pragma unroll
    for (int i = 0; i < TM; i++) {
        int row = row0 + i;
        #pragma unroll
        for (int j = 0; j < TN; j += 4) {
            int col = col0 + j;
            float4 o;
            o.x = acc[i][j + 0] + bout[col + 0];
            o.y = acc[i][j + 1] + bout[col + 1];
            o.z = acc[i][j + 2] + bout[col + 2];
            o.w = acc[i][j + 3] + bout[col + 3];
            *(float4*)(out + (size_t)row * EE + col) = o;
        }
    }
}

// ---------------- Flash attention ----------------
#define BQ 64
#define BKV 64
// 256 threads: 16x16; thread (ty,tx) owns query rows ty*4..+3.
// Score phase: key cols tx*4..+3. PV phase: output dims tx*4..+3.

__global__ __launch_bounds__(256) void attn_kernel(const int* __restrict__ mask)
{
    const int qb = blockIdx.x;   // 0..31
    const int h  = blockIdx.y;   // 0..15
    const int b  = blockIdx.z;   // 0..1
    const int q0 = qb * BQ;

    const float* Qh = g_Q + (size_t)((b * HH + h) * SS) * DD;
    const float* Kh = g_K + (size_t)((b * HH + h) * SS) * DD;
    const float* Vh = g_V + (size_t)((b * HH + h) * SS) * DD;

    __shared__ float Qs[BQ][DD];
    __shared__ float Ks[BKV][DD + 1];
    __shared__ float Vs[BKV][DD];
    __shared__ float Ps[BQ][BKV + 1];

    const int tid = threadIdx.x;
    const int tx = tid & 15;
    const int ty = tid >> 4;
    const int r0 = ty * 4;
    const int d0 = tx * 4;

    // Load Q tile (64x64)
    #pragma unroll
    for (int i = 0; i < 4; i++) {
        int vv = tid + i * 256;
        int r  = vv >> 4;
        int c  = (vv & 15) << 2;
        *(float4*)(&Qs[r][c]) = *(const float4*)(Qh + (size_t)(q0 + r) * DD + c);
    }

    float m[4], l[4], acc[4][4];
    #pragma unroll
    for (int r = 0; r < 4; r++) {
        m[r] = -INFINITY; l[r] = 0.f;
        #pragma unroll
        for (int c = 0; c < 4; c++) acc[r][c] = 0.f;
    }

    for (int kv0 = 0; kv0 < SS; kv0 += BKV) {
        // Load K (scalar stores into padded rows) and V tiles
        #pragma unroll
        for (int i = 0; i < 4; i++) {
            int vv = tid + i * 256;
            int r  = vv >> 4;
            int c  = (vv & 15) << 2;
            float4 k4 = *(const float4*)(Kh + (size_t)(kv0 + r) * DD + c);
            Ks[r][c + 0] = k4.x; Ks[r][c + 1] = k4.y;
            Ks[r][c + 2] = k4.z; Ks[r][c + 3] = k4.w;
            *(float4*)(&Vs[r][c]) = *(const float4*)(Vh + (size_t)(kv0 + r) * DD + c);
        }
        __syncthreads();

        // S = Q K^T (thread: rows r0..+3 x keys d0..+3 ... key idx = tx*4+c)
        float sv[4][4];
        #pragma unroll
        for (int r = 0; r < 4; r++)
            #pragma unroll
            for (int c = 0; c < 4; c++) sv[r][c] = 0.f;

        #pragma unroll 4
        for (int d = 0; d < DD; d++) {
            float qr[4], kc[4];
            #pragma unroll
            for (int r = 0; r < 4; r++) qr[r] = Qs[r0 + r][d];
            #pragma unroll
            for (int c = 0; c < 4; c++) kc[c] = Ks[tx * 4 + c][d];
            #pragma unroll
            for (int r = 0; r < 4; r++)
                #pragma unroll
                for (int c = 0; c < 4; c++) sv[r][c] += qr[r] * kc[c];
        }

        // scale + mask + online softmax update
        #pragma unroll
        for (int r = 0; r < 4; r++) {
            const int qg = q0 + r0 + r;
            float mx = -INFINITY;
            #pragma unroll
            for (int c = 0; c < 4; c++) {
                float s = sv[r][c] * 0.125f;   // 1/sqrt(64)
                int mv = mask[(size_t)qg * SS + kv0 + tx * 4 + c];
                s = (mv != 0) ? s : -INFINITY;
                sv[r][c] = s;
                mx = fmaxf(mx, s);
            }
            #pragma unroll
            for (int off = 1; off < 16; off <<= 1)
                mx = fmaxf(mx, __shfl_xor_sync(0xffffffffu, mx, off, 16));

            float mnew = fmaxf(m[r], mx);
            float alpha = (m[r] <= -1e30f) ? 0.f : __expf(m[r] - mnew);
            float rs = 0.f;
            #pragma unroll
            for (int c = 0; c < 4; c++) {
                float p = (sv[r][c] <= -1e30f) ? 0.f : __expf(sv[r][c] - mnew);
                Ps[r0 + r][tx * 4 + c] = p;
                rs += p;
            }
            #pragma unroll
            for (int off = 1; off < 16; off <<= 1)
                rs += __shfl_xor_sync(0xffffffffu, rs, off, 16);

            l[r] = l[r] * alpha + rs;
            m[r] = mnew;
            #pragma unroll
            for (int c = 0; c < 4; c++) acc[r][c] *= alpha;
        }
        __syncthreads();

        // acc += P @ V  (thread: rows r0..+3 x dims d0..+3)
        #pragma unroll 4
        for (int j = 0; j < BKV; j++) {
            float vr[4], pr[4];
            #pragma unroll
            for (int c = 0; c < 4; c++) vr[c] = Vs[j][d0 + c];
            #pragma unroll
            for (int r = 0; r < 4; r++) pr[r] = Ps[r0 + r][j];
            #pragma unroll
            for (int r = 0; r < 4; r++)
                #pragma unroll
                for (int c = 0; c < 4; c++) acc[r][c] += pr[r] * vr[c];
        }
        __syncthreads();
    }

    // Normalize and write ctx in [B,S,H,D] (== [B,S,E]) layout
    #pragma unroll
    for (int r = 0; r < 4; r++) {
        const int qg = q0 + r0 + r;
        float inv = 1.f / l[r];
        float4 o;
        o.x = acc[r][0] * inv;
        o.y = acc[r][1] * inv;
        o.z = acc[r][2] * inv;
        o.w = acc[r][3] * inv;
        *(float4*)(g_ctx + (size_t)((b * SS + qg) * HH + h) * DD + d0) = o;
    }
}

extern "C" void kernel_launch(void* const* d_in, const int* in_sizes, int n_in,
                              void* d_out, int out_size)
{
    const float* q    = (const float*)d_in[0];
    const float* k    = (const float*)d_in[1];
    const float* v    = (const float*)d_in[2];
    const int*   mask = (const int*)  d_in[3];
    const float* Wqkv = (const float*)d_in[4];
    const float* bqkv = (const float*)d_in[5];
    const float* Wout = (const float*)d_in[6];
    const float* bout = (const float*)d_in[7];
    float* out = (float*)d_out;

    dim3 gqkv(EE / BN, (BB * SS) / BM, 3);      // (8, 32, 3)
    qkv_gemm<<<gqkv, 256>>>(q, k, v, Wqkv, bqkv);

    dim3 gattn(SS / BQ, HH, BB);                 // (32, 16, 2)
    attn_kernel<<<gattn, 256>>>(mask);

    dim3 gout(EE / BN, (BB * SS) / BM, 1);      // (8, 32)
    out_gemm<<<gout, 256>>>(Wout, bout, out);
}

// round 3
// speedup vs baseline: 1.3117x; 1.3117x over previous
#include <cuda_runtime.h>
#include <cuda_bf16.h>
#include <cstdint>
#include <math.h>

#define BB 2
#define SS 2048
#define EE 1024
#define HH 16
#define DD 64
#define MT 4096          // rows per GEMM (B*S)

// ---------------- scratch (__device__ globals; no allocs allowed) ----------------
__device__ float g_Q[BB*HH*SS*DD];
__device__ float g_K[BB*HH*SS*DD];
__device__ float g_V[BB*HH*SS*DD];
__device__ float g_ctx[BB*SS*EE];

__device__ __nv_bfloat16 g_Ahi[3*MT*EE];     // q,k,v activations hi
__device__ __nv_bfloat16 g_Alo[3*MT*EE];     // residual lo
__device__ __nv_bfloat16 g_Whi[4*EE*EE];     // W^T rows: [0,3072)=qkv, [3072,4096)=out
__device__ __nv_bfloat16 g_Wlo[4*EE*EE];
__device__ __nv_bfloat16 g_Chi[MT*EE];       // ctx hi
__device__ __nv_bfloat16 g_Clo[MT*EE];

// ---------------- helpers ----------------
__device__ __forceinline__ uint32_t smem_u32(const void* p) {
    uint32_t a;
    asm("{ .reg .u64 t; cvta.to.shared.u64 t, %1; cvt.u32.u64 %0, t; }" : "=r"(a) : "l"(p));
    return a;
}
__device__ __forceinline__ uint32_t sw128(uint32_t off) { return off ^ ((off >> 3) & 0x70); }

__device__ __forceinline__ void cp_async16(uint32_t dst, const void* src) {
    asm volatile("cp.async.cg.shared.global [%0], [%1], 16;" :: "r"(dst), "l"(src) : "memory");
}
__device__ __forceinline__ void cp_commit() {
    asm volatile("cp.async.commit_group;" ::: "memory");
}
template <int N> __device__ __forceinline__ void cp_wait() {
    asm volatile("cp.async.wait_group %0;" :: "n"(N) : "memory");
}
__device__ __forceinline__ void ldsm_x4(uint32_t addr, uint32_t& r0, uint32_t& r1, uint32_t& r2, uint32_t& r3) {
    asm volatile("ldmatrix.sync.aligned.m8n8.x4.shared.b16 {%0,%1,%2,%3}, [%4];"
        : "=r"(r0), "=r"(r1), "=r"(r2), "=r"(r3) : "r"(addr));
}
__device__ __forceinline__ void mma16816(float* c, const uint32_t* a, uint32_t b0, uint32_t b1) {
    asm volatile("mma.sync.aligned.m16n8k16.row.col.f32.bf16.bf16.f32 "
        "{%0,%1,%2,%3}, {%4,%5,%6,%7}, {%8,%9}, {%0,%1,%2,%3};"
        : "+f"(c[0]), "+f"(c[1]), "+f"(c[2]), "+f"(c[3])
        : "r"(a[0]), "r"(a[1]), "r"(a[2]), "r"(a[3]), "r"(b0), "r"(b1));
}

// ---------------- conversion kernels ----------------
__global__ __launch_bounds__(256) void conv_rows(
    const float* __restrict__ src, __nv_bfloat16* __restrict__ dhi, __nv_bfloat16* __restrict__ dlo)
{
    int idx = blockIdx.x * 256 + threadIdx.x;   // float4 index
    float4 x = ((const float4*)src)[idx];
    __nv_bfloat16 hh[4], ll[4];
    float xs[4] = {x.x, x.y, x.z, x.w};
    #pragma unroll
    for (int i = 0; i < 4; i++) {
        hh[i] = __float2bfloat16(xs[i]);
        ll[i] = __float2bfloat16(xs[i] - __bfloat162float(hh[i]));
    }
    *(uint2*)&dhi[(size_t)idx * 4] = *(uint2*)hh;
    *(uint2*)&dlo[(size_t)idx * 4] = *(uint2*)ll;
}

// Transpose W [1024 k][ldn n] -> W^T rows (n-major, k contiguous), bf16 hi/lo
__global__ __launch_bounds__(256) void conv_wT(
    const float* __restrict__ W, int ldn,
    __nv_bfloat16* __restrict__ dhi, __nv_bfloat16* __restrict__ dlo)
{
    __shared__ float t[32][33];
    const int n0 = blockIdx.x * 32;
    const int k0 = blockIdx.y * 32;
    const int tid = threadIdx.x;
    {
        int tx = tid & 31, ty = tid >> 5;
        #pragma unroll
        for (int r = 0; r < 4; r++) {
            int k = ty + r * 8;
            t[tx][k] = W[(size_t)(k0 + k) * ldn + n0 + tx];
        }
    }
    __syncthreads();
    {
        int tkg = tid & 7, tn = tid >> 3;
        __nv_bfloat16 hh[4], ll[4];
        #pragma unroll
        for (int i = 0; i < 4; i++) {
            float v = t[tn][tkg * 4 + i];
            hh[i] = __float2bfloat16(v);
            ll[i] = __float2bfloat16(v - __bfloat162float(hh[i]));
        }
        size_t off = (size_t)(n0 + tn) * EE + k0 + tkg * 4;
        *(uint2*)&dhi[off] = *(uint2*)hh;
        *(uint2*)&dlo[off] = *(uint2*)ll;
    }
}

// ---------------- HMMA GEMM: C[128x128] = A[128x1024] * W^T + bias ----------------
// 256 threads = 8 warps (4 M x 2 N), warp tile 32x64. K-chunks of 64 bf16 (128B rows, SW128).
// Buffers: per chunk, 4 tiles (A_hi, A_lo, B_hi, B_lo) x 16KB; double buffered = 128KB dyn smem.
#define TILE_B 16384
#define BUF_B  (4 * TILE_B)
#define SMEM_TOTAL (2 * BUF_B)
#define NCHUNK 16

template <int MODE>
__global__ __launch_bounds__(256) void mma_gemm(
    const __nv_bfloat16* __restrict__ Ahi, const __nv_bfloat16* __restrict__ Alo,
    const float* __restrict__ bias_all, float* __restrict__ out1)
{
    extern __shared__ char smem[];
    const uint32_t sb = smem_u32(smem);
    const int tid = threadIdx.x;
    const int wid = tid >> 5;
    const int lane = tid & 31;
    const int warp_m = wid & 3;
    const int warp_n = wid >> 2;

    const int n0 = blockIdx.x * 128;
    const int m0 = blockIdx.y * 128;
    int z = 0, wbase;
    if (MODE == 0) { z = blockIdx.z; wbase = z * EE; } else { wbase = 3 * EE; }

    const uint4* gsrc[4];
    gsrc[0] = (const uint4*)(Ahi + ((MODE == 0) ? (size_t)z * MT * EE : 0) + (size_t)m0 * EE);
    gsrc[1] = (const uint4*)(Alo + ((MODE == 0) ? (size_t)z * MT * EE : 0) + (size_t)m0 * EE);
    gsrc[2] = (const uint4*)(g_Whi + (size_t)(wbase + n0) * EE);
    gsrc[3] = (const uint4*)(g_Wlo + (size_t)(wbase + n0) * EE);

    float acc[2][8][4];
    #pragma unroll
    for (int mt = 0; mt < 2; mt++)
        #pragma unroll
        for (int nt = 0; nt < 8; nt++)
            #pragma unroll
            for (int i = 0; i < 4; i++) acc[mt][nt][i] = 0.f;

    // per-thread load coords (8 uint4 per tile-row-block: tid -> (r, j))
    const int lr = tid >> 3;          // 0..31  (row group base; 4 rows per iter)
    const int lj = tid & 7;           // 0..7   (16B column)

    auto load_chunk = [&](int c) {
        const uint32_t bbase = sb + (c & 1) * BUF_B;
        #pragma unroll
        for (int arr = 0; arr < 4; arr++) {
            const uint4* gp = gsrc[arr];
            const uint32_t tb = bbase + arr * TILE_B;
            #pragma unroll
            for (int u = 0; u < 4; u++) {
                int r = lr + u * 32;
                uint32_t dst = tb + sw128((uint32_t)(r * 128 + lj * 16));
                cp_async16(dst, gp + (size_t)r * 128 + c * 8 + lj);
            }
        }
        cp_commit();
    };

    load_chunk(0);

    for (int c = 0; c < NCHUNK; c++) {
        if (c + 1 < NCHUNK) { load_chunk(c + 1); cp_wait<1>(); }
        else                { cp_wait<0>(); }
        __syncthreads();

        const uint32_t bbase = sb + (c & 1) * BUF_B;
        #pragma unroll
        for (int combo = 0; combo < 3; combo++) {
            const uint32_t aT = bbase + ((combo == 2) ? TILE_B : 0);
            const uint32_t bT = bbase + 2 * TILE_B + ((combo == 1) ? TILE_B : 0);
            #pragma unroll
            for (int kk = 0; kk < 4; kk++) {
                uint32_t a[2][4];
                #pragma unroll
                for (int mt = 0; mt < 2; mt++) {
                    int row = warp_m * 32 + mt * 16 + (lane & 15);
                    int ch  = kk * 2 + (lane >> 4);
                    ldsm_x4(aT + sw128((uint32_t)(row * 128 + ch * 16)),
                            a[mt][0], a[mt][1], a[mt][2], a[mt][3]);
                }
                uint32_t b[4][4];
                #pragma unroll
                for (int p = 0; p < 4; p++) {
                    int nr = warp_n * 64 + p * 16 + ((lane & 7) | ((lane & 16) >> 1));
                    int ch = kk * 2 + ((lane >> 3) & 1);
                    ldsm_x4(bT + sw128((uint32_t)(nr * 128 + ch * 16)),
                            b[p][0], b[p][1], b[p][2], b[p][3]);
                }
                #pragma unroll
                for (int mt = 0; mt < 2; mt++)
                    #pragma unroll
                    for (int nt = 0; nt < 8; nt++)
                        mma16816(acc[mt][nt], a[mt], b[nt >> 1][(nt & 1) * 2], b[nt >> 1][(nt & 1) * 2 + 1]);
            }
        }
        __syncthreads();
    }

    // ---------------- epilogue ----------------
    const float* bias = bias_all + ((MODE == 0) ? z * EE : 0);
    float* outp;
    if (MODE == 0) outp = (z == 0) ? g_Q : (z == 1) ? g_K : g_V;
    else           outp = out1;

    #pragma unroll
    for (int mt = 0; mt < 2; mt++) {
        #pragma unroll
        for (int nt = 0; nt < 8; nt++) {
            const int col = n0 + warp_n * 64 + nt * 8 + (lane & 3) * 2;
            const float bx = bias[col], by = bias[col + 1];
            #pragma unroll
            for (int half = 0; half < 2; half++) {
                const int row = m0 + warp_m * 32 + mt * 16 + (lane >> 2) + half * 8;
                float2 o;
                o.x = acc[mt][nt][half * 2 + 0] + bx;
                o.y = acc[mt][nt][half * 2 + 1] + by;
                if (MODE == 0) {
                    const int bb = row >> 11, s = row & (SS - 1);
                    const int h = col >> 6, d = col & 63;
                    *(float2*)(outp + (((size_t)(bb * HH + h) * SS + s) * DD) + d) = o;
                } else {
                    *(float2*)(outp + (size_t)row * EE + col) = o;
                }
            }
        }
    }
}

// ---------------- Flash attention (unchanged FFMA path) ----------------
#define BQ 64
#define BKV 64

__global__ __launch_bounds__(256) void attn_kernel(const int* __restrict__ mask)
{
    const int qb = blockIdx.x;
    const int h  = blockIdx.y;
    const int b  = blockIdx.z;
    const int q0 = qb * BQ;

    const float* Qh = g_Q + (size_t)((b * HH + h) * SS) * DD;
    const float* Kh = g_K + (size_t)((b * HH + h) * SS) * DD;
    const float* Vh = g_V + (size_t)((b * HH + h) * SS) * DD;

    __shared__ float Qs[BQ][DD];
    __shared__ float Ks[BKV][DD + 1];
    __shared__ float Vs[BKV][DD];
    __shared__ float Ps[BQ][BKV + 1];

    const int tid = threadIdx.x;
    const int tx = tid & 15;
    const int ty = tid >> 4;
    const int r0 = ty * 4;
    const int d0 = tx * 4;

    #pragma unroll
    for (int i = 0; i < 4; i++) {
        int vv = tid + i * 256;
        int r  = vv >> 4;
        int c  = (vv & 15) << 2;
        *(float4*)(&Qs[r][c]) = *(const float4*)(Qh + (size_t)(q0 + r) * DD + c);
    }

    float m[4], l[4], acc[4][4];
    #pragma unroll
    for (int r = 0; r < 4; r++) {
        m[r] = -INFINITY; l[r] = 0.f;
        #pragma unroll
        for (int c = 0; c < 4; c++) acc[r][c] = 0.f;
    }

    for (int kv0 = 0; kv0 < SS; kv0 += BKV) {
        #pragma unroll
        for (int i = 0; i < 4; i++) {
            int vv = tid + i * 256;
            int r  = vv >> 4;
            int c  = (vv & 15) << 2;
            float4 k4 = *(const float4*)(Kh + (size_t)(kv0 + r) * DD + c);
            Ks[r][c + 0] = k4.x; Ks[r][c + 1] = k4.y;
            Ks[r][c + 2] = k4.z; Ks[r][c + 3] = k4.w;
            *(float4*)(&Vs[r][c]) = *(const float4*)(Vh + (size_t)(kv0 + r) * DD + c);
        }
        __syncthreads();

        float sv[4][4];
        #pragma unroll
        for (int r = 0; r < 4; r++)
            #pragma unroll
            for (int c = 0; c < 4; c++) sv[r][c] = 0.f;

        #pragma unroll 4
        for (int d = 0; d < DD; d++) {
            float qr[4], kc[4];
            #pragma unroll
            for (int r = 0; r < 4; r++) qr[r] = Qs[r0 + r][d];
            #pragma unroll
            for (int c = 0; c < 4; c++) kc[c] = Ks[tx * 4 + c][d];
            #pragma unroll
            for (int r = 0; r < 4; r++)
                #pragma unroll
                for (int c = 0; c < 4; c++) sv[r][c] += qr[r] * kc[c];
        }

        #pragma unroll
        for (int r = 0; r < 4; r++) {
            const int qg = q0 + r0 + r;
            float mx = -INFINITY;
            #pragma unroll
            for (int c = 0; c < 4; c++) {
                float s = sv[r][c] * 0.125f;
                int mv = mask[(size_t)qg * SS + kv0 + tx * 4 + c];
                s = (mv != 0) ? s : -INFINITY;
                sv[r][c] = s;
                mx = fmaxf(mx, s);
            }
            #pragma unroll
            for (int off = 1; off < 16; off <<= 1)
                mx = fmaxf(mx, __shfl_xor_sync(0xffffffffu, mx, off, 16));

            float mnew = fmaxf(m[r], mx);
            float alpha = (m[r] <= -1e30f) ? 0.f : __expf(m[r] - mnew);
            float rs = 0.f;
            #pragma unroll
            for (int c = 0; c < 4; c++) {
                float p = (sv[r][c] <= -1e30f) ? 0.f : __expf(sv[r][c] - mnew);
                Ps[r0 + r][tx * 4 + c] = p;
                rs += p;
            }
            #pragma unroll
            for (int off = 1; off < 16; off <<= 1)
                rs += __shfl_xor_sync(0xffffffffu, rs, off, 16);

            l[r] = l[r] * alpha + rs;
            m[r] = mnew;
            #pragma unroll
            for (int c = 0; c < 4; c++) acc[r][c] *= alpha;
        }
        __syncthreads();

        #pragma unroll 4
        for (int j = 0; j < BKV; j++) {
            float vr[4], pr[4];
            #pragma unroll
            for (int c = 0; c < 4; c++) vr[c] = Vs[j][d0 + c];
            #pragma unroll
            for (int r = 0; r < 4; r++) pr[r] = Ps[r0 + r][j];
            #pragma unroll
            for (int r = 0; r < 4; r++)
                #pragma unroll
                for (int c = 0; c < 4; c++) acc[r][c] += pr[r] * vr[c];
        }
        __syncthreads();
    }

    #pragma unroll
    for (int r = 0; r < 4; r++) {
        const int qg = q0 + r0 + r;
        float inv = 1.f / l[r];
        float4 o;
        o.x = acc[r][0] * inv;
        o.y = acc[r][1] * inv;
        o.z = acc[r][2] * inv;
        o.w = acc[r][3] * inv;
        *(float4*)(g_ctx + (size_t)((b * SS + qg) * HH + h) * DD + d0) = o;
    }
}

// ---------------- launch ----------------
extern "C" void kernel_launch(void* const* d_in, const int* in_sizes, int n_in,
                              void* d_out, int out_size)
{
    const float* q    = (const float*)d_in[0];
    const float* k    = (const float*)d_in[1];
    const float* v    = (const float*)d_in[2];
    const int*   mask = (const int*)  d_in[3];
    const float* Wqkv = (const float*)d_in[4];
    const float* bqkv = (const float*)d_in[5];
    const float* Wout = (const float*)d_in[6];
    const float* bout = (const float*)d_in[7];
    float* out = (float*)d_out;

    cudaFuncSetAttribute(mma_gemm<0>, cudaFuncAttributeMaxDynamicSharedMemorySize, SMEM_TOTAL);
    cudaFuncSetAttribute(mma_gemm<1>, cudaFuncAttributeMaxDynamicSharedMemorySize, SMEM_TOTAL);

    __nv_bfloat16 *Ahi, *Alo, *Whi, *Wlo, *Chi, *Clo;
    cudaGetSymbolAddress((void**)&Ahi, g_Ahi);
    cudaGetSymbolAddress((void**)&Alo, g_Alo);
    cudaGetSymbolAddress((void**)&Whi, g_Whi);
    cudaGetSymbolAddress((void**)&Wlo, g_Wlo);
    cudaGetSymbolAddress((void**)&Chi, g_Chi);
    cudaGetSymbolAddress((void**)&Clo, g_Clo);

    const int n4 = MT * EE / 4;           // float4s per activation matrix
    conv_rows<<<n4 / 256, 256>>>(q, Ahi + 0 * (size_t)MT * EE, Alo + 0 * (size_t)MT * EE);
    conv_rows<<<n4 / 256, 256>>>(k, Ahi + 1 * (size_t)MT * EE, Alo + 1 * (size_t)MT * EE);
    conv_rows<<<n4 / 256, 256>>>(v, Ahi + 2 * (size_t)MT * EE, Alo + 2 * (size_t)MT * EE);

    conv_wT<<<dim3(3 * EE / 32, EE / 32), 256>>>(Wqkv, 3 * EE, Whi, Wlo);
    conv_wT<<<dim3(EE / 32, EE / 32), 256>>>(Wout, EE, Whi + (size_t)3 * EE * EE, Wlo + (size_t)3 * EE * EE);

    mma_gemm<0><<<dim3(EE / 128, MT / 128, 3), 256, SMEM_TOTAL>>>(Ahi, Alo, bqkv, nullptr);

    attn_kernel<<<dim3(SS / BQ, HH, BB), 256>>>(mask);

    float* ctx; cudaGetSymbolAddress((void**)&ctx, g_ctx);
    conv_rows<<<n4 / 256, 256>>>(ctx, Chi, Clo);

    mma_gemm<1><<<dim3(EE / 128, MT / 128, 1), 256, SMEM_TOTAL>>>(Chi, Clo, bout, out);
}

// round 4
// speedup vs baseline: 2.9213x; 2.2271x over previous
#include <cuda_runtime.h>
#include <cuda_bf16.h>
#include <cstdint>
#include <math.h>

#define BB 2
#define SS 2048
#define EE 1024
#define HH 16
#define DD 64
#define MT 4096          // rows per GEMM (B*S)

// ---------------- scratch (__device__ globals; no allocs allowed) ----------------
__device__ __nv_bfloat16 g_Ahi[3*MT*EE];     // q,k,v activations hi
__device__ __nv_bfloat16 g_Alo[3*MT*EE];     // residual lo
__device__ __nv_bfloat16 g_Whi[4*EE*EE];     // W^T rows: [0,3072)=qkv, [3072,4096)=out
__device__ __nv_bfloat16 g_Wlo[4*EE*EE];

__device__ __nv_bfloat16 g_Qhi[BB*HH*SS*DD]; // pre-scaled by 0.125, [b,h][s][d]
__device__ __nv_bfloat16 g_Qlo[BB*HH*SS*DD];
__device__ __nv_bfloat16 g_Khi[BB*HH*SS*DD]; // [b,h][s][d]
__device__ __nv_bfloat16 g_Klo[BB*HH*SS*DD];
__device__ __nv_bfloat16 g_VThi[BB*HH*DD*SS]; // transposed: [b,h][d][s]
__device__ __nv_bfloat16 g_VTlo[BB*HH*DD*SS];

__device__ __nv_bfloat16 g_Chi[MT*EE];       // ctx hi   [b,s][e]
__device__ __nv_bfloat16 g_Clo[MT*EE];
__device__ uint32_t g_mb[SS*(SS/32)];        // mask bits [q][kword]

// ---------------- helpers ----------------
__device__ __forceinline__ uint32_t smem_u32(const void* p) {
    uint32_t a;
    asm("{ .reg .u64 t; cvta.to.shared.u64 t, %1; cvt.u32.u64 %0, t; }" : "=r"(a) : "l"(p));
    return a;
}
__device__ __forceinline__ uint32_t sw128(uint32_t off) { return off ^ ((off >> 3) & 0x70); }

__device__ __forceinline__ void cp_async16(uint32_t dst, const void* src) {
    asm volatile("cp.async.cg.shared.global [%0], [%1], 16;" :: "r"(dst), "l"(src) : "memory");
}
__device__ __forceinline__ void cp_async8(uint32_t dst, const void* src) {
    asm volatile("cp.async.ca.shared.global [%0], [%1], 8;" :: "r"(dst), "l"(src) : "memory");
}
__device__ __forceinline__ void cp_commit() {
    asm volatile("cp.async.commit_group;" ::: "memory");
}
template <int N> __device__ __forceinline__ void cp_wait() {
    asm volatile("cp.async.wait_group %0;" :: "n"(N) : "memory");
}
__device__ __forceinline__ void ldsm_x4(uint32_t addr, uint32_t& r0, uint32_t& r1, uint32_t& r2, uint32_t& r3) {
    asm volatile("ldmatrix.sync.aligned.m8n8.x4.shared.b16 {%0,%1,%2,%3}, [%4];"
        : "=r"(r0), "=r"(r1), "=r"(r2), "=r"(r3) : "r"(addr));
}
__device__ __forceinline__ void mma16816(float* c, const uint32_t* a, uint32_t b0, uint32_t b1) {
    asm volatile("mma.sync.aligned.m16n8k16.row.col.f32.bf16.bf16.f32 "
        "{%0,%1,%2,%3}, {%4,%5,%6,%7}, {%8,%9}, {%0,%1,%2,%3};"
        : "+f"(c[0]), "+f"(c[1]), "+f"(c[2]), "+f"(c[3])
        : "r"(a[0]), "r"(a[1]), "r"(a[2]), "r"(a[3]), "r"(b0), "r"(b1));
}

// ---------------- conversion kernels ----------------
__global__ __launch_bounds__(256) void conv_rows(
    const float* __restrict__ src, __nv_bfloat16* __restrict__ dhi, __nv_bfloat16* __restrict__ dlo)
{
    int idx = blockIdx.x * 256 + threadIdx.x;
    float4 x = ((const float4*)src)[idx];
    __nv_bfloat16 hh[4], ll[4];
    float xs[4] = {x.x, x.y, x.z, x.w};
    #pragma unroll
    for (int i = 0; i < 4; i++) {
        hh[i] = __float2bfloat16(xs[i]);
        ll[i] = __float2bfloat16(xs[i] - __bfloat162float(hh[i]));
    }
    *(uint2*)&dhi[(size_t)idx * 4] = *(uint2*)hh;
    *(uint2*)&dlo[(size_t)idx * 4] = *(uint2*)ll;
}

__global__ __launch_bounds__(256) void conv_wT(
    const float* __restrict__ W, int ldn,
    __nv_bfloat16* __restrict__ dhi, __nv_bfloat16* __restrict__ dlo)
{
    __shared__ float t[32][33];
    const int n0 = blockIdx.x * 32;
    const int k0 = blockIdx.y * 32;
    const int tid = threadIdx.x;
    {
        int tx = tid & 31, ty = tid >> 5;
        #pragma unroll
        for (int r = 0; r < 4; r++) {
            int k = ty + r * 8;
            t[tx][k] = W[(size_t)(k0 + k) * ldn + n0 + tx];
        }
    }
    __syncthreads();
    {
        int tkg = tid & 7, tn = tid >> 3;
        __nv_bfloat16 hh[4], ll[4];
        #pragma unroll
        for (int i = 0; i < 4; i++) {
            float v = t[tn][tkg * 4 + i];
            hh[i] = __float2bfloat16(v);
            ll[i] = __float2bfloat16(v - __bfloat162float(hh[i]));
        }
        size_t off = (size_t)(n0 + tn) * EE + k0 + tkg * 4;
        *(uint2*)&dhi[off] = *(uint2*)hh;
        *(uint2*)&dlo[off] = *(uint2*)ll;
    }
}

// mask [S][S] int32 -> bit words [S][S/32]; one warp per word, ballot.
__global__ __launch_bounds__(256) void mask_bits(const int* __restrict__ mask)
{
    int gw = blockIdx.x * 8 + (threadIdx.x >> 5);   // global word id
    int lane = threadIdx.x & 31;
    int q = gw >> 6, w = gw & 63;
    int v = mask[(size_t)q * SS + w * 32 + lane];
    uint32_t bits = __ballot_sync(0xffffffffu, v != 0);
    if (lane == 0) g_mb[gw] = bits;
}

// ---------------- HMMA GEMM (R3-proven) with new MODE0 epilogue ----------------
#define TILE_B 16384
#define BUF_B  (4 * TILE_B)
#define GEMM_SMEM (2 * BUF_B)
#define NCHUNK 16

template <int MODE>
__global__ __launch_bounds__(256) void mma_gemm(
    const __nv_bfloat16* __restrict__ Ahi, const __nv_bfloat16* __restrict__ Alo,
    const float* __restrict__ bias_all, float* __restrict__ out1)
{
    extern __shared__ char smem[];
    const uint32_t sb = smem_u32(smem);
    const int tid = threadIdx.x;
    const int wid = tid >> 5;
    const int lane = tid & 31;
    const int warp_m = wid & 3;
    const int warp_n = wid >> 2;

    const int n0 = blockIdx.x * 128;
    const int m0 = blockIdx.y * 128;
    int z = 0, wbase;
    if (MODE == 0) { z = blockIdx.z; wbase = z * EE; } else { wbase = 3 * EE; }

    const uint4* gsrc[4];
    gsrc[0] = (const uint4*)(Ahi + ((MODE == 0) ? (size_t)z * MT * EE : 0) + (size_t)m0 * EE);
    gsrc[1] = (const uint4*)(Alo + ((MODE == 0) ? (size_t)z * MT * EE : 0) + (size_t)m0 * EE);
    gsrc[2] = (const uint4*)(g_Whi + (size_t)(wbase + n0) * EE);
    gsrc[3] = (const uint4*)(g_Wlo + (size_t)(wbase + n0) * EE);

    float acc[2][8][4];
    #pragma unroll
    for (int mt = 0; mt < 2; mt++)
        #pragma unroll
        for (int nt = 0; nt < 8; nt++)
            #pragma unroll
            for (int i = 0; i < 4; i++) acc[mt][nt][i] = 0.f;

    const int lr = tid >> 3;
    const int lj = tid & 7;

    auto load_chunk = [&](int c) {
        const uint32_t bbase = sb + (c & 1) * BUF_B;
        #pragma unroll
        for (int arr = 0; arr < 4; arr++) {
            const uint4* gp = gsrc[arr];
            const uint32_t tb = bbase + arr * TILE_B;
            #pragma unroll
            for (int u = 0; u < 4; u++) {
                int r = lr + u * 32;
                uint32_t dst = tb + sw128((uint32_t)(r * 128 + lj * 16));
                cp_async16(dst, gp + (size_t)r * 128 + c * 8 + lj);
            }
        }
        cp_commit();
    };

    load_chunk(0);

    for (int c = 0; c < NCHUNK; c++) {
        if (c + 1 < NCHUNK) { load_chunk(c + 1); cp_wait<1>(); }
        else                { cp_wait<0>(); }
        __syncthreads();

        const uint32_t bbase = sb + (c & 1) * BUF_B;
        #pragma unroll
        for (int combo = 0; combo < 3; combo++) {
            const uint32_t aT = bbase + ((combo == 2) ? TILE_B : 0);
            const uint32_t bT = bbase + 2 * TILE_B + ((combo == 1) ? TILE_B : 0);
            #pragma unroll
            for (int kk = 0; kk < 4; kk++) {
                uint32_t a[2][4];
                #pragma unroll
                for (int mt = 0; mt < 2; mt++) {
                    int row = warp_m * 32 + mt * 16 + (lane & 15);
                    int ch  = kk * 2 + (lane >> 4);
                    ldsm_x4(aT + sw128((uint32_t)(row * 128 + ch * 16)),
                            a[mt][0], a[mt][1], a[mt][2], a[mt][3]);
                }
                uint32_t b[4][4];
                #pragma unroll
                for (int p = 0; p < 4; p++) {
                    int nr = warp_n * 64 + p * 16 + ((lane & 7) | ((lane & 16) >> 1));
                    int ch = kk * 2 + ((lane >> 3) & 1);
                    ldsm_x4(bT + sw128((uint32_t)(nr * 128 + ch * 16)),
                            b[p][0], b[p][1], b[p][2], b[p][3]);
                }
                #pragma unroll
                for (int mt = 0; mt < 2; mt++)
                    #pragma unroll
                    for (int nt = 0; nt < 8; nt++)
                        mma16816(acc[mt][nt], a[mt], b[nt >> 1][(nt & 1) * 2], b[nt >> 1][(nt & 1) * 2 + 1]);
            }
        }
        __syncthreads();
    }

    // ---------------- epilogue ----------------
    if (MODE == 0) {
        const float* bias = bias_all + z * EE;
        #pragma unroll
        for (int mt = 0; mt < 2; mt++) {
            #pragma unroll
            for (int nt = 0; nt < 8; nt++) {
                const int col = n0 + warp_n * 64 + nt * 8 + (lane & 3) * 2;   // 0..1023
                const int hh2 = col >> 6, dd2 = col & 63;
                const float bx = bias[col], by = bias[col + 1];
                #pragma unroll
                for (int half = 0; half < 2; half++) {
                    const int row = m0 + warp_m * 32 + mt * 16 + (lane >> 2) + half * 8;
                    const int bb = row >> 11, s = row & (SS - 1);
                    const int bhx = bb * HH + hh2;
                    float v0 = acc[mt][nt][half * 2 + 0] + bx;
                    float v1 = acc[mt][nt][half * 2 + 1] + by;
                    if (z == 0) { v0 *= 0.125f; v1 *= 0.125f; }
                    __nv_bfloat16 h0 = __float2bfloat16(v0);
                    __nv_bfloat16 h1 = __float2bfloat16(v1);
                    __nv_bfloat16 l0 = __float2bfloat16(v0 - __bfloat162float(h0));
                    __nv_bfloat16 l1 = __float2bfloat16(v1 - __bfloat162float(h1));
                    if (z == 2) {
                        size_t o0 = ((size_t)bhx * DD + dd2) * SS + s;
                        size_t o1 = ((size_t)bhx * DD + dd2 + 1) * SS + s;
                        g_VThi[o0] = h0; g_VThi[o1] = h1;
                        g_VTlo[o0] = l0; g_VTlo[o1] = l1;
                    } else {
                        size_t off = ((size_t)bhx * SS + s) * DD + dd2;
                        __nv_bfloat16* dh = (z == 0) ? g_Qhi : g_Khi;
                        __nv_bfloat16* dl = (z == 0) ? g_Qlo : g_Klo;
                        __nv_bfloat162 ph; ph.x = h0; ph.y = h1;
                        __nv_bfloat162 pl; pl.x = l0; pl.y = l1;
                        *(__nv_bfloat162*)(dh + off) = ph;
                        *(__nv_bfloat162*)(dl + off) = pl;
                    }
                }
            }
        }
    } else {
        const float* bias = bias_all;
        #pragma unroll
        for (int mt = 0; mt < 2; mt++) {
            #pragma unroll
            for (int nt = 0; nt < 8; nt++) {
                const int col = n0 + warp_n * 64 + nt * 8 + (lane & 3) * 2;
                const float bx = bias[col], by = bias[col + 1];
                #pragma unroll
                for (int half = 0; half < 2; half++) {
                    const int row = m0 + warp_m * 32 + mt * 16 + (lane >> 2) + half * 8;
                    float2 o;
                    o.x = acc[mt][nt][half * 2 + 0] + bx;
                    o.y = acc[mt][nt][half * 2 + 1] + by;
                    *(float2*)(out1 + (size_t)row * EE + col) = o;
                }
            }
        }
    }
}

// ---------------- tensor-core flash attention ----------------
// CTA: (q-tile 128, head, batch). 8 warps x 16 q-rows. KV tiles of 64 keys.
#define AQ 128
#define AK 64
#define NKV (SS / AK)            // 32
#define A_OFF_Q    0             // Qhi 16KB, Qlo 16KB
#define A_BUF0     32768
#define A_BUFSZ    33792         // Khi 8K, Klo 8K, VThi 8K, VTlo 8K, mask 1K
#define A_OFF_KHI  0
#define A_OFF_KLO  8192
#define A_OFF_VHI  16384
#define A_OFF_VLO  24576
#define A_OFF_MB   32768
#define ATTN_SMEM  (A_BUF0 + 2 * A_BUFSZ)   // 100352

__global__ __launch_bounds__(256) void attn_mma()
{
    extern __shared__ char smem[];
    const uint32_t sb = smem_u32(smem);
    const int tid = threadIdx.x;
    const int lane = tid & 31;
    const int warp = tid >> 5;

    const int q0 = blockIdx.x * AQ;
    const int h  = blockIdx.y;
    const int b  = blockIdx.z;
    const int bh = b * HH + h;

    const uint4* gQh = (const uint4*)(g_Qhi + (size_t)bh * SS * DD);
    const uint4* gQl = (const uint4*)(g_Qlo + (size_t)bh * SS * DD);
    const uint4* gKh = (const uint4*)(g_Khi + (size_t)bh * SS * DD);
    const uint4* gKl = (const uint4*)(g_Klo + (size_t)bh * SS * DD);
    const uint4* gVh = (const uint4*)(g_VThi + (size_t)bh * DD * SS);
    const uint4* gVl = (const uint4*)(g_VTlo + (size_t)bh * DD * SS);

    const int lr = tid >> 3;        // 0..31
    const int lj = tid & 7;         // 0..7

    // issue Q (one group)
    {
        #pragma unroll
        for (int u = 0; u < 4; u++) {
            int r = lr + u * 32;    // 0..127
            uint32_t off = sw128((uint32_t)(r * 128 + lj * 16));
            cp_async16(sb + A_OFF_Q + off,          gQh + (size_t)(q0 + r) * 8 + lj);
            cp_async16(sb + A_OFF_Q + 16384 + off,  gQl + (size_t)(q0 + r) * 8 + lj);
        }
        cp_commit();
    }

    auto issue_tile = [&](int t) {
        if (t < NKV) {
            const int kv0 = t * AK;
            const uint32_t bbase = sb + A_BUF0 + (t & 1) * A_BUFSZ;
            #pragma unroll
            for (int u = 0; u < 2; u++) {
                int r = lr + u * 32;    // 0..63
                uint32_t off = sw128((uint32_t)(r * 128 + lj * 16));
                cp_async16(bbase + A_OFF_KHI + off, gKh + (size_t)(kv0 + r) * 8 + lj);
                cp_async16(bbase + A_OFF_KLO + off, gKl + (size_t)(kv0 + r) * 8 + lj);
                cp_async16(bbase + A_OFF_VHI + off, gVh + (size_t)r * 256 + kv0 / 8 + lj);
                cp_async16(bbase + A_OFF_VLO + off, gVl + (size_t)r * 256 + kv0 / 8 + lj);
            }
            if (tid < AQ)
                cp_async8(bbase + A_OFF_MB + tid * 8,
                          g_mb + (size_t)(q0 + tid) * (SS / 32) + kv0 / 32);
        }
        cp_commit();
    };

    issue_tile(0);

    uint32_t qh[4][4], ql[4][4];
    float mcur[2] = {-1e38f, -1e38f};
    float lcur[2] = {0.f, 0.f};
    float acc[8][4];
    #pragma unroll
    for (int nt = 0; nt < 8; nt++)
        #pragma unroll
        for (int i = 0; i < 4; i++) acc[nt][i] = 0.f;

    for (int t = 0; t < NKV; t++) {
        issue_tile(t + 1);
        cp_wait<1>();
        __syncthreads();

        if (t == 0) {
            // load Q A-frags once
            #pragma unroll
            for (int kk = 0; kk < 4; kk++) {
                int row = warp * 16 + (lane & 15);
                int ch  = kk * 2 + (lane >> 4);
                uint32_t off = sw128((uint32_t)(row * 128 + ch * 16));
                ldsm_x4(sb + A_OFF_Q + off,         qh[kk][0], qh[kk][1], qh[kk][2], qh[kk][3]);
                ldsm_x4(sb + A_OFF_Q + 16384 + off, ql[kk][0], ql[kk][1], ql[kk][2], ql[kk][3]);
            }
        }

        const uint32_t bbase = sb + A_BUF0 + (t & 1) * A_BUFSZ;

        // ---- scores: S[128 x 64] hi/lo 3-pass ----
        float s[8][4];
        #pragma unroll
        for (int nt = 0; nt < 8; nt++)
            #pragma unroll
            for (int i = 0; i < 4; i++) s[nt][i] = 0.f;

        #pragma unroll
        for (int kk = 0; kk < 4; kk++) {
            uint32_t bhif[4][4], blof[4][4];
            #pragma unroll
            for (int p = 0; p < 4; p++) {
                int nr = p * 16 + ((lane & 7) | ((lane & 16) >> 1));
                int ch = kk * 2 + ((lane >> 3) & 1);
                uint32_t off = sw128((uint32_t)(nr * 128 + ch * 16));
                ldsm_x4(bbase + A_OFF_KHI + off, bhif[p][0], bhif[p][1], bhif[p][2], bhif[p][3]);
                ldsm_x4(bbase + A_OFF_KLO + off, blof[p][0], blof[p][1], blof[p][2], blof[p][3]);
            }
            #pragma unroll
            for (int nt = 0; nt < 8; nt++) {
                uint32_t b0 = bhif[nt >> 1][(nt & 1) * 2], b1 = bhif[nt >> 1][(nt & 1) * 2 + 1];
                uint32_t c0 = blof[nt >> 1][(nt & 1) * 2], c1 = blof[nt >> 1][(nt & 1) * 2 + 1];
                mma16816(s[nt], qh[kk], b0, b1);
                mma16816(s[nt], qh[kk], c0, c1);
                mma16816(s[nt], ql[kk], b0, b1);
            }
        }

        // ---- mask + online softmax ----
        uint32_t mw[2][2];
        {
            const uint32_t mbase = bbase + A_OFF_MB;
            #pragma unroll
            for (int hf = 0; hf < 2; hf++) {
                int row = warp * 16 + (lane >> 2) + hf * 8;
                mw[hf][0] = *(const uint32_t*)(smem + (mbase - sb) + row * 8);
                mw[hf][1] = *(const uint32_t*)(smem + (mbase - sb) + row * 8 + 4);
            }
        }
        float mx[2] = {-1e38f, -1e38f};
        #pragma unroll
        for (int nt = 0; nt < 8; nt++) {
            int w = nt >> 2;
            int bp0 = ((nt & 3) << 3) + 2 * (lane & 3);
            s[nt][0] = ((mw[0][w] >> bp0) & 1)       ? s[nt][0] : -1e38f;
            s[nt][1] = ((mw[0][w] >> (bp0 + 1)) & 1) ? s[nt][1] : -1e38f;
            s[nt][2] = ((mw[1][w] >> bp0) & 1)       ? s[nt][2] : -1e38f;
            s[nt][3] = ((mw[1][w] >> (bp0 + 1)) & 1) ? s[nt][3] : -1e38f;
            mx[0] = fmaxf(mx[0], fmaxf(s[nt][0], s[nt][1]));
            mx[1] = fmaxf(mx[1], fmaxf(s[nt][2], s[nt][3]));
        }
        #pragma unroll
        for (int hf = 0; hf < 2; hf++) {
            mx[hf] = fmaxf(mx[hf], __shfl_xor_sync(0xffffffffu, mx[hf], 1));
            mx[hf] = fmaxf(mx[hf], __shfl_xor_sync(0xffffffffu, mx[hf], 2));
        }
        float al[2], mn[2];
        #pragma unroll
        for (int hf = 0; hf < 2; hf++) {
            mn[hf] = fmaxf(mcur[hf], mx[hf]);
            al[hf] = __expf(mcur[hf] - mn[hf]);
        }
        float rs[2] = {0.f, 0.f};
        #pragma unroll
        for (int nt = 0; nt < 8; nt++) {
            s[nt][0] = __expf(s[nt][0] - mn[0]);
            s[nt][1] = __expf(s[nt][1] - mn[0]);
            s[nt][2] = __expf(s[nt][2] - mn[1]);
            s[nt][3] = __expf(s[nt][3] - mn[1]);
            rs[0] += s[nt][0] + s[nt][1];
            rs[1] += s[nt][2] + s[nt][3];
        }
        #pragma unroll
        for (int hf = 0; hf < 2; hf++) {
            rs[hf] += __shfl_xor_sync(0xffffffffu, rs[hf], 1);
            rs[hf] += __shfl_xor_sync(0xffffffffu, rs[hf], 2);
            lcur[hf] = lcur[hf] * al[hf] + rs[hf];
            mcur[hf] = mn[hf];
        }
        #pragma unroll
        for (int nt = 0; nt < 8; nt++) {
            acc[nt][0] *= al[0]; acc[nt][1] *= al[0];
            acc[nt][2] *= al[1]; acc[nt][3] *= al[1];
        }

        // ---- PV: acc += P[128x64] * V[64x64], hi/lo 3-pass ----
        #pragma unroll
        for (int kk = 0; kk < 4; kk++) {
            // pack P frags from score C-frags of ntiles 2kk, 2kk+1
            uint32_t ahif[4], alof[4];
            #pragma unroll
            for (int q2 = 0; q2 < 4; q2++) {
                const int nt = 2 * kk + (q2 >> 1);
                const int i0 = (q2 & 1) * 2;
                float p0 = s[nt][i0], p1 = s[nt][i0 + 1];
                __nv_bfloat162 hp = __floats2bfloat162_rn(p0, p1);
                float r0 = p0 - __bfloat162float(hp.x);
                float r1 = p1 - __bfloat162float(hp.y);
                __nv_bfloat162 lp = __floats2bfloat162_rn(r0, r1);
                ahif[q2] = *(uint32_t*)&hp;
                alof[q2] = *(uint32_t*)&lp;
            }
            // reorder to (a0,a1,a2,a3) = (nt2kk:c01, nt2kk:c23, nt2kk+1:c01, nt2kk+1:c23)
            uint32_t ah[4] = { ahif[0], ahif[1], ahif[2], ahif[3] };
            uint32_t alo2[4] = { alof[0], alof[1], alof[2], alof[3] };

            uint32_t vh[4][4], vl[4][4];
            #pragma unroll
            for (int p = 0; p < 4; p++) {
                int nr = p * 16 + ((lane & 7) | ((lane & 16) >> 1));
                int ch = kk * 2 + ((lane >> 3) & 1);
                uint32_t off = sw128((uint32_t)(nr * 128 + ch * 16));
                ldsm_x4(bbase + A_OFF_VHI + off, vh[p][0], vh[p][1], vh[p][2], vh[p][3]);
                ldsm_x4(bbase + A_OFF_VLO + off, vl[p][0], vl[p][1], vl[p][2], vl[p][3]);
            }
            #pragma unroll
            for (int nt = 0; nt < 8; nt++) {
                uint32_t b0 = vh[nt >> 1][(nt & 1) * 2], b1 = vh[nt >> 1][(nt & 1) * 2 + 1];
                uint32_t c0 = vl[nt >> 1][(nt & 1) * 2], c1 = vl[nt >> 1][(nt & 1) * 2 + 1];
                mma16816(acc[nt], ah, b0, b1);
                mma16816(acc[nt], ah, c0, c1);
                mma16816(acc[nt], alo2, b0, b1);
            }
        }
        __syncthreads();
    }

    // ---- epilogue: normalize, split hi/lo, write ctx bf16 ----
    float inv[2];
    inv[0] = 1.f / lcur[0];
    inv[1] = 1.f / lcur[1];
    #pragma unroll
    for (int nt = 0; nt < 8; nt++) {
        const int d = nt * 8 + (lane & 3) * 2;
        #pragma unroll
        for (int hf = 0; hf < 2; hf++) {
            const int row = q0 + warp * 16 + (lane >> 2) + hf * 8;
            float v0 = acc[nt][hf * 2 + 0] * inv[hf];
            float v1 = acc[nt][hf * 2 + 1] * inv[hf];
            __nv_bfloat16 h0 = __float2bfloat16(v0);
            __nv_bfloat16 h1 = __float2bfloat16(v1);
            __nv_bfloat162 ph; ph.x = h0; ph.y = h1;
            __nv_bfloat162 pl;
            pl.x = __float2bfloat16(v0 - __bfloat162float(h0));
            pl.y = __float2bfloat16(v1 - __bfloat162float(h1));
            size_t off = ((size_t)(b * SS + row)) * EE + h * DD + d;
            *(__nv_bfloat162*)(g_Chi + off) = ph;
            *(__nv_bfloat162*)(g_Clo + off) = pl;
        }
    }
}

// ---------------- launch ----------------
extern "C" void kernel_launch(void* const* d_in, const int* in_sizes, int n_in,
                              void* d_out, int out_size)
{
    const float* q    = (const float*)d_in[0];
    const float* k    = (const float*)d_in[1];
    const float* v    = (const float*)d_in[2];
    const int*   mask = (const int*)  d_in[3];
    const float* Wqkv = (const float*)d_in[4];
    const float* bqkv = (const float*)d_in[5];
    const float* Wout = (const float*)d_in[6];
    const float* bout = (const float*)d_in[7];
    float* out = (float*)d_out;

    cudaFuncSetAttribute(mma_gemm<0>, cudaFuncAttributeMaxDynamicSharedMemorySize, GEMM_SMEM);
    cudaFuncSetAttribute(mma_gemm<1>, cudaFuncAttributeMaxDynamicSharedMemorySize, GEMM_SMEM);
    cudaFuncSetAttribute(attn_mma,    cudaFuncAttributeMaxDynamicSharedMemorySize, ATTN_SMEM);

    __nv_bfloat16 *Ahi, *Alo, *Whi, *Wlo, *Chi, *Clo;
    cudaGetSymbolAddress((void**)&Ahi, g_Ahi);
    cudaGetSymbolAddress((void**)&Alo, g_Alo);
    cudaGetSymbolAddress((void**)&Whi, g_Whi);
    cudaGetSymbolAddress((void**)&Wlo, g_Wlo);
    cudaGetSymbolAddress((void**)&Chi, g_Chi);
    cudaGetSymbolAddress((void**)&Clo, g_Clo);

    const int n4 = MT * EE / 4;
    conv_rows<<<n4 / 256, 256>>>(q, Ahi + 0 * (size_t)MT * EE, Alo + 0 * (size_t)MT * EE);
    conv_rows<<<n4 / 256, 256>>>(k, Ahi + 1 * (size_t)MT * EE, Alo + 1 * (size_t)MT * EE);
    conv_rows<<<n4 / 256, 256>>>(v, Ahi + 2 * (size_t)MT * EE, Alo + 2 * (size_t)MT * EE);

    conv_wT<<<dim3(3 * EE / 32, EE / 32), 256>>>(Wqkv, 3 * EE, Whi, Wlo);
    conv_wT<<<dim3(EE / 32, EE / 32), 256>>>(Wout, EE, Whi + (size_t)3 * EE * EE, Wlo + (size_t)3 * EE * EE);

    mask_bits<<<SS * (SS / 32) / 8, 256>>>(mask);

    mma_gemm<0><<<dim3(EE / 128, MT / 128, 3), 256, GEMM_SMEM>>>(Ahi, Alo, bqkv, nullptr);

    attn_mma<<<dim3(SS / AQ, HH, BB), 256, ATTN_SMEM>>>();

    mma_gemm<1><<<dim3(EE / 128, MT / 128, 1), 256, GEMM_SMEM>>>(Chi, Clo, bout, out);
}

// round 5
// speedup vs baseline: 3.1037x; 1.0624x over previous
#include <cuda_runtime.h>
#include <cuda_bf16.h>
#include <cstdint>
#include <math.h>

#define BB 2
#define SS 2048
#define EE 1024
#define HH 16
#define DD 64
#define MT 4096          // rows per GEMM (B*S)

// ---------------- scratch (__device__ globals; no allocs allowed) ----------------
__device__ __nv_bfloat16 g_Ahi[3*MT*EE];     // q,k,v activations hi
__device__ __nv_bfloat16 g_Alo[3*MT*EE];     // residual lo
__device__ __nv_bfloat16 g_Whi[4*EE*EE];     // W^T rows: [0,3072)=qkv, [3072,4096)=out
__device__ __nv_bfloat16 g_Wlo[4*EE*EE];

__device__ __nv_bfloat16 g_Qhi[BB*HH*SS*DD]; // pre-scaled by 0.125, [b,h][s][d]
__device__ __nv_bfloat16 g_Qlo[BB*HH*SS*DD];
__device__ __nv_bfloat16 g_Khi[BB*HH*SS*DD]; // [b,h][s][d]
__device__ __nv_bfloat16 g_Klo[BB*HH*SS*DD];
__device__ __nv_bfloat16 g_VThi[BB*HH*DD*SS]; // transposed: [b,h][d][s]
__device__ __nv_bfloat16 g_VTlo[BB*HH*DD*SS];

__device__ __nv_bfloat16 g_Chi[MT*EE];       // ctx hi   [b,s][e]
__device__ __nv_bfloat16 g_Clo[MT*EE];
__device__ uint32_t g_mb[SS*(SS/32)];        // mask bits [q][kword]

// ---------------- helpers ----------------
__device__ __forceinline__ uint32_t smem_u32(const void* p) {
    uint32_t a;
    asm("{ .reg .u64 t; cvta.to.shared.u64 t, %1; cvt.u32.u64 %0, t; }" : "=r"(a) : "l"(p));
    return a;
}
__device__ __forceinline__ uint32_t sw128(uint32_t off) { return off ^ ((off >> 3) & 0x70); }
__device__ __forceinline__ uint32_t sw256(uint32_t off) { return off ^ ((off >> 4) & 0x70); }

__device__ __forceinline__ void cp_async16(uint32_t dst, const void* src) {
    asm volatile("cp.async.cg.shared.global [%0], [%1], 16;" :: "r"(dst), "l"(src) : "memory");
}
__device__ __forceinline__ void cp_commit() {
    asm volatile("cp.async.commit_group;" ::: "memory");
}
template <int N> __device__ __forceinline__ void cp_wait() {
    asm volatile("cp.async.wait_group %0;" :: "n"(N) : "memory");
}
__device__ __forceinline__ void ldsm_x4(uint32_t addr, uint32_t& r0, uint32_t& r1, uint32_t& r2, uint32_t& r3) {
    asm volatile("ldmatrix.sync.aligned.m8n8.x4.shared.b16 {%0,%1,%2,%3}, [%4];"
        : "=r"(r0), "=r"(r1), "=r"(r2), "=r"(r3) : "r"(addr));
}
__device__ __forceinline__ void mma16816(float* c, const uint32_t* a, uint32_t b0, uint32_t b1) {
    asm volatile("mma.sync.aligned.m16n8k16.row.col.f32.bf16.bf16.f32 "
        "{%0,%1,%2,%3}, {%4,%5,%6,%7}, {%8,%9}, {%0,%1,%2,%3};"
        : "+f"(c[0]), "+f"(c[1]), "+f"(c[2]), "+f"(c[3])
        : "r"(a[0]), "r"(a[1]), "r"(a[2]), "r"(a[3]), "r"(b0), "r"(b1));
}

// ---------------- conversion kernels ----------------
__global__ __launch_bounds__(256) void conv_rows3(
    const float* __restrict__ q, const float* __restrict__ k, const float* __restrict__ v,
    __nv_bfloat16* __restrict__ dhi, __nv_bfloat16* __restrict__ dlo)
{
    const int z = blockIdx.y;
    const float* src = (z == 0) ? q : (z == 1) ? k : v;
    size_t base = (size_t)z * MT * EE;
    int idx = blockIdx.x * 256 + threadIdx.x;
    float4 x = ((const float4*)src)[idx];
    __nv_bfloat16 hh[4], ll[4];
    float xs[4] = {x.x, x.y, x.z, x.w};
    #pragma unroll
    for (int i = 0; i < 4; i++) {
        hh[i] = __float2bfloat16(xs[i]);
        ll[i] = __float2bfloat16(xs[i] - __bfloat162float(hh[i]));
    }
    *(uint2*)&dhi[base + (size_t)idx * 4] = *(uint2*)hh;
    *(uint2*)&dlo[base + (size_t)idx * 4] = *(uint2*)ll;
}

__global__ __launch_bounds__(256) void conv_wT(
    const float* __restrict__ W, int ldn,
    __nv_bfloat16* __restrict__ dhi, __nv_bfloat16* __restrict__ dlo)
{
    __shared__ float t[32][33];
    const int n0 = blockIdx.x * 32;
    const int k0 = blockIdx.y * 32;
    const int tid = threadIdx.x;
    {
        int tx = tid & 31, ty = tid >> 5;
        #pragma unroll
        for (int r = 0; r < 4; r++) {
            int k = ty + r * 8;
            t[tx][k] = W[(size_t)(k0 + k) * ldn + n0 + tx];
        }
    }
    __syncthreads();
    {
        int tkg = tid & 7, tn = tid >> 3;
        __nv_bfloat16 hh[4], ll[4];
        #pragma unroll
        for (int i = 0; i < 4; i++) {
            float v = t[tn][tkg * 4 + i];
            hh[i] = __float2bfloat16(v);
            ll[i] = __float2bfloat16(v - __bfloat162float(hh[i]));
        }
        size_t off = (size_t)(n0 + tn) * EE + k0 + tkg * 4;
        *(uint2*)&dhi[off] = *(uint2*)hh;
        *(uint2*)&dlo[off] = *(uint2*)ll;
    }
}

__global__ __launch_bounds__(256) void mask_bits(const int* __restrict__ mask)
{
    int gw = blockIdx.x * 8 + (threadIdx.x >> 5);
    int lane = threadIdx.x & 31;
    int q = gw >> 6, w = gw & 63;
    int v = mask[(size_t)q * SS + w * 32 + lane];
    uint32_t bits = __ballot_sync(0xffffffffu, v != 0);
    if (lane == 0) g_mb[gw] = bits;
}

// ---------------- HMMA GEMM ----------------
#define TILE_B 16384
#define BUF_B  (4 * TILE_B)
#define GEMM_SMEM (2 * BUF_B)
#define NCHUNK 16

template <int MODE>
__global__ __launch_bounds__(256) void mma_gemm(
    const __nv_bfloat16* __restrict__ Ahi, const __nv_bfloat16* __restrict__ Alo,
    const float* __restrict__ bias_all, float* __restrict__ out1)
{
    extern __shared__ char smem[];
    const uint32_t sb = smem_u32(smem);
    const int tid = threadIdx.x;
    const int wid = tid >> 5;
    const int lane = tid & 31;
    const int warp_m = wid & 3;
    const int warp_n = wid >> 2;

    const int n0 = blockIdx.x * 128;
    const int m0 = blockIdx.y * 128;
    int z = 0, wbase;
    if (MODE == 0) { z = blockIdx.z; wbase = z * EE; } else { wbase = 3 * EE; }

    const uint4* gsrc[4];
    gsrc[0] = (const uint4*)(Ahi + ((MODE == 0) ? (size_t)z * MT * EE : 0) + (size_t)m0 * EE);
    gsrc[1] = (const uint4*)(Alo + ((MODE == 0) ? (size_t)z * MT * EE : 0) + (size_t)m0 * EE);
    gsrc[2] = (const uint4*)(g_Whi + (size_t)(wbase + n0) * EE);
    gsrc[3] = (const uint4*)(g_Wlo + (size_t)(wbase + n0) * EE);

    float acc[2][8][4];
    #pragma unroll
    for (int mt = 0; mt < 2; mt++)
        #pragma unroll
        for (int nt = 0; nt < 8; nt++)
            #pragma unroll
            for (int i = 0; i < 4; i++) acc[mt][nt][i] = 0.f;

    const int lr = tid >> 3;
    const int lj = tid & 7;

    auto load_chunk = [&](int c) {
        const uint32_t bbase = sb + (c & 1) * BUF_B;
        #pragma unroll
        for (int arr = 0; arr < 4; arr++) {
            const uint4* gp = gsrc[arr];
            const uint32_t tb = bbase + arr * TILE_B;
            #pragma unroll
            for (int u = 0; u < 4; u++) {
                int r = lr + u * 32;
                uint32_t dst = tb + sw128((uint32_t)(r * 128 + lj * 16));
                cp_async16(dst, gp + (size_t)r * 128 + c * 8 + lj);
            }
        }
        cp_commit();
    };

    load_chunk(0);

    for (int c = 0; c < NCHUNK; c++) {
        if (c + 1 < NCHUNK) { load_chunk(c + 1); cp_wait<1>(); }
        else                { cp_wait<0>(); }
        __syncthreads();

        const uint32_t bbase = sb + (c & 1) * BUF_B;
        #pragma unroll
        for (int kk = 0; kk < 4; kk++) {
            uint32_t ah[2][4], al2[2][4];
            #pragma unroll
            for (int mt = 0; mt < 2; mt++) {
                int row = warp_m * 32 + mt * 16 + (lane & 15);
                int ch  = kk * 2 + (lane >> 4);
                uint32_t off = sw128((uint32_t)(row * 128 + ch * 16));
                ldsm_x4(bbase + 0 * TILE_B + off, ah[mt][0], ah[mt][1], ah[mt][2], ah[mt][3]);
                ldsm_x4(bbase + 1 * TILE_B + off, al2[mt][0], al2[mt][1], al2[mt][2], al2[mt][3]);
            }
            #pragma unroll
            for (int p = 0; p < 4; p++) {
                int nr = warp_n * 64 + p * 16 + ((lane & 7) | ((lane & 16) >> 1));
                int ch = kk * 2 + ((lane >> 3) & 1);
                uint32_t off = sw128((uint32_t)(nr * 128 + ch * 16));
                uint32_t bh4[4], bl4[4];
                ldsm_x4(bbase + 2 * TILE_B + off, bh4[0], bh4[1], bh4[2], bh4[3]);
                ldsm_x4(bbase + 3 * TILE_B + off, bl4[0], bl4[1], bl4[2], bl4[3]);
                #pragma unroll
                for (int mt = 0; mt < 2; mt++) {
                    #pragma unroll
                    for (int half = 0; half < 2; half++) {
                        const int nt = p * 2 + half;
                        mma16816(acc[mt][nt], ah[mt],  bh4[half * 2], bh4[half * 2 + 1]);
                        mma16816(acc[mt][nt], ah[mt],  bl4[half * 2], bl4[half * 2 + 1]);
                        mma16816(acc[mt][nt], al2[mt], bh4[half * 2], bh4[half * 2 + 1]);
                    }
                }
            }
        }
        __syncthreads();
    }

    // ---------------- epilogue ----------------
    if (MODE == 0) {
        const float* bias = bias_all + z * EE;
        if (z == 2) {
            // stage through smem, write VT coalesced
            __syncthreads();
            float* st = (float*)smem;
            const int STR = 132;
            #pragma unroll
            for (int mt = 0; mt < 2; mt++) {
                #pragma unroll
                for (int nt = 0; nt < 8; nt++) {
                    const int col_l = warp_n * 64 + nt * 8 + (lane & 3) * 2;
                    const float bx = bias[n0 + col_l], by = bias[n0 + col_l + 1];
                    #pragma unroll
                    for (int half = 0; half < 2; half++) {
                        const int row_l = warp_m * 32 + mt * 16 + (lane >> 2) + half * 8;
                        st[col_l * STR + row_l]       = acc[mt][nt][half * 2 + 0] + bx;
                        st[(col_l + 1) * STR + row_l] = acc[mt][nt][half * 2 + 1] + by;
                    }
                }
            }
            __syncthreads();
            const int nl = tid >> 1;            // 0..127  (local col = (h,d))
            const int mh = (tid & 1) * 64;      // m half
            const int col = n0 + nl;
            const int h = col >> 6, d = col & 63;
            const int row0g = m0 + mh;
            const int bbv = row0g >> 11, s0 = row0g & (SS - 1);
            size_t base = ((size_t)(bbv * HH + h) * DD + d) * SS + s0;
            const float* srow = st + nl * STR + mh;
            #pragma unroll
            for (int i = 0; i < 64; i += 4) {
                float4 xv = *(const float4*)(srow + i);
                __nv_bfloat16 h4[4], l4[4];
                float xs[4] = {xv.x, xv.y, xv.z, xv.w};
                #pragma unroll
                for (int j = 0; j < 4; j++) {
                    h4[j] = __float2bfloat16(xs[j]);
                    l4[j] = __float2bfloat16(xs[j] - __bfloat162float(h4[j]));
                }
                *(uint2*)(g_VThi + base + i) = *(uint2*)h4;
                *(uint2*)(g_VTlo + base + i) = *(uint2*)l4;
            }
        } else {
            #pragma unroll
            for (int mt = 0; mt < 2; mt++) {
                #pragma unroll
                for (int nt = 0; nt < 8; nt++) {
                    const int col = n0 + warp_n * 64 + nt * 8 + (lane & 3) * 2;
                    const int hh2 = col >> 6, dd2 = col & 63;
                    const float bx = bias[col], by = bias[col + 1];
                    #pragma unroll
                    for (int half = 0; half < 2; half++) {
                        const int row = m0 + warp_m * 32 + mt * 16 + (lane >> 2) + half * 8;
                        const int bb = row >> 11, s = row & (SS - 1);
                        const int bhx = bb * HH + hh2;
                        float v0 = acc[mt][nt][half * 2 + 0] + bx;
                        float v1 = acc[mt][nt][half * 2 + 1] + by;
                        if (z == 0) { v0 *= 0.125f; v1 *= 0.125f; }
                        __nv_bfloat16 h0 = __float2bfloat16(v0);
                        __nv_bfloat16 h1 = __float2bfloat16(v1);
                        size_t off = ((size_t)bhx * SS + s) * DD + dd2;
                        __nv_bfloat16* dh = (z == 0) ? g_Qhi : g_Khi;
                        __nv_bfloat16* dl = (z == 0) ? g_Qlo : g_Klo;
                        __nv_bfloat162 ph; ph.x = h0; ph.y = h1;
                        __nv_bfloat162 pl;
                        pl.x = __float2bfloat16(v0 - __bfloat162float(h0));
                        pl.y = __float2bfloat16(v1 - __bfloat162float(h1));
                        *(__nv_bfloat162*)(dh + off) = ph;
                        *(__nv_bfloat162*)(dl + off) = pl;
                    }
                }
            }
        }
    } else {
        const float* bias = bias_all;
        #pragma unroll
        for (int mt = 0; mt < 2; mt++) {
            #pragma unroll
            for (int nt = 0; nt < 8; nt++) {
                const int col = n0 + warp_n * 64 + nt * 8 + (lane & 3) * 2;
                const float bx = bias[col], by = bias[col + 1];
                #pragma unroll
                for (int half = 0; half < 2; half++) {
                    const int row = m0 + warp_m * 32 + mt * 16 + (lane >> 2) + half * 8;
                    float2 o;
                    o.x = acc[mt][nt][half * 2 + 0] + bx;
                    o.y = acc[mt][nt][half * 2 + 1] + by;
                    *(float2*)(out1 + (size_t)row * EE + col) = o;
                }
            }
        }
    }
}

// ---------------- tensor-core flash attention, AK=128 ----------------
#define AQ 128
#define AK 128
#define NKV (SS / AK)            // 16
#define A_OFF_Q    0             // Qhi 16KB, Qlo 16KB
#define A_BUF0     32768
#define A_OFF_KHI  0
#define A_OFF_KLO  16384
#define A_OFF_VHI  32768
#define A_OFF_VLO  49152
#define A_OFF_MB   65536
#define A_BUFSZ    67584         // 64K tiles + 2K mask (+pad)
#define ATTN_SMEM  (A_BUF0 + 2 * A_BUFSZ)   // 167936

__global__ __launch_bounds__(256) void attn_mma()
{
    extern __shared__ char smem[];
    const uint32_t sb = smem_u32(smem);
    const int tid = threadIdx.x;
    const int lane = tid & 31;
    const int warp = tid >> 5;

    const int q0 = blockIdx.x * AQ;
    const int h  = blockIdx.y;
    const int b  = blockIdx.z;
    const int bh = b * HH + h;

    const uint4* gQh = (const uint4*)(g_Qhi + (size_t)bh * SS * DD);
    const uint4* gQl = (const uint4*)(g_Qlo + (size_t)bh * SS * DD);
    const uint4* gKh = (const uint4*)(g_Khi + (size_t)bh * SS * DD);
    const uint4* gKl = (const uint4*)(g_Klo + (size_t)bh * SS * DD);
    const uint4* gVh = (const uint4*)(g_VThi + (size_t)bh * DD * SS);
    const uint4* gVl = (const uint4*)(g_VTlo + (size_t)bh * DD * SS);

    const int lr = tid >> 3;        // 0..31
    const int lj = tid & 7;         // 0..7
    const int vr = tid >> 4;        // 0..15
    const int vj = tid & 15;        // 0..15

    // issue Q
    {
        #pragma unroll
        for (int u = 0; u < 4; u++) {
            int r = lr + u * 32;
            uint32_t off = sw128((uint32_t)(r * 128 + lj * 16));
            cp_async16(sb + A_OFF_Q + off,          gQh + (size_t)(q0 + r) * 8 + lj);
            cp_async16(sb + A_OFF_Q + 16384 + off,  gQl + (size_t)(q0 + r) * 8 + lj);
        }
        cp_commit();
    }

    auto issue_tile = [&](int t) {
        if (t < NKV) {
            const int kv0 = t * AK;
            const uint32_t bbase = sb + A_BUF0 + (t & 1) * A_BUFSZ;
            #pragma unroll
            for (int u = 0; u < 4; u++) {
                int r = lr + u * 32;        // 0..127 (K rows)
                uint32_t off = sw128((uint32_t)(r * 128 + lj * 16));
                cp_async16(bbase + A_OFF_KHI + off, gKh + (size_t)(kv0 + r) * 8 + lj);
                cp_async16(bbase + A_OFF_KLO + off, gKl + (size_t)(kv0 + r) * 8 + lj);
            }
            #pragma unroll
            for (int u = 0; u < 4; u++) {
                int r = vr + u * 16;        // 0..63 (V d-rows)
                uint32_t off = sw256((uint32_t)(r * 256 + vj * 16));
                cp_async16(bbase + A_OFF_VHI + off, gVh + (size_t)r * 256 + kv0 / 8 + vj);
                cp_async16(bbase + A_OFF_VLO + off, gVl + (size_t)r * 256 + kv0 / 8 + vj);
            }
            if (tid < AQ)
                cp_async16(bbase + A_OFF_MB + tid * 16,
                           g_mb + (size_t)(q0 + tid) * (SS / 32) + kv0 / 32);
        }
        cp_commit();
    };

    issue_tile(0);

    uint32_t qh[4][4], ql[4][4];
    float mcur[2] = {-1e38f, -1e38f};
    float lcur[2] = {0.f, 0.f};
    float acc[8][4];
    #pragma unroll
    for (int nt = 0; nt < 8; nt++)
        #pragma unroll
        for (int i = 0; i < 4; i++) acc[nt][i] = 0.f;

    for (int t = 0; t < NKV; t++) {
        issue_tile(t + 1);
        cp_wait<1>();
        __syncthreads();

        if (t == 0) {
            #pragma unroll
            for (int kk = 0; kk < 4; kk++) {
                int row = warp * 16 + (lane & 15);
                int ch  = kk * 2 + (lane >> 4);
                uint32_t off = sw128((uint32_t)(row * 128 + ch * 16));
                ldsm_x4(sb + A_OFF_Q + off,         qh[kk][0], qh[kk][1], qh[kk][2], qh[kk][3]);
                ldsm_x4(sb + A_OFF_Q + 16384 + off, ql[kk][0], ql[kk][1], ql[kk][2], ql[kk][3]);
            }
        }

        const uint32_t bbase = sb + A_BUF0 + (t & 1) * A_BUFSZ;

        // ---- scores: S[128 x 128] hi/lo 3-pass ----
        float s[16][4];
        #pragma unroll
        for (int nt = 0; nt < 16; nt++)
            #pragma unroll
            for (int i = 0; i < 4; i++) s[nt][i] = 0.f;

        #pragma unroll
        for (int kk = 0; kk < 4; kk++) {
            #pragma unroll
            for (int p = 0; p < 8; p++) {
                int nr = p * 16 + ((lane & 7) | ((lane & 16) >> 1));
                int ch = kk * 2 + ((lane >> 3) & 1);
                uint32_t off = sw128((uint32_t)(nr * 128 + ch * 16));
                uint32_t bh4[4], bl4[4];
                ldsm_x4(bbase + A_OFF_KHI + off, bh4[0], bh4[1], bh4[2], bh4[3]);
                ldsm_x4(bbase + A_OFF_KLO + off, bl4[0], bl4[1], bl4[2], bl4[3]);
                #pragma unroll
                for (int half = 0; half < 2; half++) {
                    const int nt = p * 2 + half;
                    mma16816(s[nt], qh[kk], bh4[half * 2], bh4[half * 2 + 1]);
                    mma16816(s[nt], qh[kk], bl4[half * 2], bl4[half * 2 + 1]);
                    mma16816(s[nt], ql[kk], bh4[half * 2], bh4[half * 2 + 1]);
                }
            }
        }

        // ---- mask + online softmax ----
        uint32_t mw[2][4];
        #pragma unroll
        for (int hf = 0; hf < 2; hf++) {
            int row = warp * 16 + (lane >> 2) + hf * 8;
            uint4 m4 = *(const uint4*)(smem + (A_BUF0 + (t & 1) * A_BUFSZ + A_OFF_MB) + row * 16);
            mw[hf][0] = m4.x; mw[hf][1] = m4.y; mw[hf][2] = m4.z; mw[hf][3] = m4.w;
        }
        float mx[2] = {-1e38f, -1e38f};
        #pragma unroll
        for (int nt = 0; nt < 16; nt++) {
            int w = nt >> 2;
            int bp0 = ((nt & 3) << 3) + 2 * (lane & 3);
            s[nt][0] = ((mw[0][w] >> bp0) & 1)       ? s[nt][0] : -1e38f;
            s[nt][1] = ((mw[0][w] >> (bp0 + 1)) & 1) ? s[nt][1] : -1e38f;
            s[nt][2] = ((mw[1][w] >> bp0) & 1)       ? s[nt][2] : -1e38f;
            s[nt][3] = ((mw[1][w] >> (bp0 + 1)) & 1) ? s[nt][3] : -1e38f;
            mx[0] = fmaxf(mx[0], fmaxf(s[nt][0], s[nt][1]));
            mx[1] = fmaxf(mx[1], fmaxf(s[nt][2], s[nt][3]));
        }
        #pragma unroll
        for (int hf = 0; hf < 2; hf++) {
            mx[hf] = fmaxf(mx[hf], __shfl_xor_sync(0xffffffffu, mx[hf], 1));
            mx[hf] = fmaxf(mx[hf], __shfl_xor_sync(0xffffffffu, mx[hf], 2));
        }
        float al[2], mn[2];
        #pragma unroll
        for (int hf = 0; hf < 2; hf++) {
            mn[hf] = fmaxf(mcur[hf], mx[hf]);
            al[hf] = __expf(mcur[hf] - mn[hf]);
        }
        float rs[2] = {0.f, 0.f};
        #pragma unroll
        for (int nt = 0; nt < 16; nt++) {
            s[nt][0] = __expf(s[nt][0] - mn[0]);
            s[nt][1] = __expf(s[nt][1] - mn[0]);
            s[nt][2] = __expf(s[nt][2] - mn[1]);
            s[nt][3] = __expf(s[nt][3] - mn[1]);
            rs[0] += s[nt][0] + s[nt][1];
            rs[1] += s[nt][2] + s[nt][3];
        }
        #pragma unroll
        for (int hf = 0; hf < 2; hf++) {
            rs[hf] += __shfl_xor_sync(0xffffffffu, rs[hf], 1);
            rs[hf] += __shfl_xor_sync(0xffffffffu, rs[hf], 2);
            lcur[hf] = lcur[hf] * al[hf] + rs[hf];
            mcur[hf] = mn[hf];
        }
        #pragma unroll
        for (int nt = 0; nt < 8; nt++) {
            acc[nt][0] *= al[0]; acc[nt][1] *= al[0];
            acc[nt][2] *= al[1]; acc[nt][3] *= al[1];
        }

        // ---- PV: acc += P[128x128] * V[128x64], hi/lo 3-pass ----
        #pragma unroll
        for (int kk = 0; kk < 8; kk++) {
            uint32_t ah4[4], al4[4];
            #pragma unroll
            for (int q2 = 0; q2 < 4; q2++) {
                const int nt = 2 * kk + (q2 >> 1);
                const int i0 = (q2 & 1) * 2;
                float p0 = s[nt][i0], p1 = s[nt][i0 + 1];
                __nv_bfloat162 hp = __floats2bfloat162_rn(p0, p1);
                float r0 = p0 - __bfloat162float(hp.x);
                float r1 = p1 - __bfloat162float(hp.y);
                __nv_bfloat162 lp = __floats2bfloat162_rn(r0, r1);
                ah4[q2] = *(uint32_t*)&hp;
                al4[q2] = *(uint32_t*)&lp;
            }
            #pragma unroll
            for (int p = 0; p < 4; p++) {
                int nr = p * 16 + ((lane & 7) | ((lane & 16) >> 1));
                int ch = kk * 2 + ((lane >> 3) & 1);
                uint32_t off = sw256((uint32_t)(nr * 256 + ch * 16));
                uint32_t vh4[4], vl4[4];
                ldsm_x4(bbase + A_OFF_VHI + off, vh4[0], vh4[1], vh4[2], vh4[3]);
                ldsm_x4(bbase + A_OFF_VLO + off, vl4[0], vl4[1], vl4[2], vl4[3]);
                #pragma unroll
                for (int half = 0; half < 2; half++) {
                    const int nt2 = p * 2 + half;
                    mma16816(acc[nt2], ah4, vh4[half * 2], vh4[half * 2 + 1]);
                    mma16816(acc[nt2], ah4, vl4[half * 2], vl4[half * 2 + 1]);
                    mma16816(acc[nt2], al4, vh4[half * 2], vh4[half * 2 + 1]);
                }
            }
        }
        __syncthreads();
    }

    // ---- epilogue ----
    float inv[2];
    inv[0] = 1.f / lcur[0];
    inv[1] = 1.f / lcur[1];
    #pragma unroll
    for (int nt = 0; nt < 8; nt++) {
        const int d = nt * 8 + (lane & 3) * 2;
        #pragma unroll
        for (int hf = 0; hf < 2; hf++) {
            const int row = q0 + warp * 16 + (lane >> 2) + hf * 8;
            float v0 = acc[nt][hf * 2 + 0] * inv[hf];
            float v1 = acc[nt][hf * 2 + 1] * inv[hf];
            __nv_bfloat16 h0 = __float2bfloat16(v0);
            __nv_bfloat16 h1 = __float2bfloat16(v1);
            __nv_bfloat162 ph; ph.x = h0; ph.y = h1;
            __nv_bfloat162 pl;
            pl.x = __float2bfloat16(v0 - __bfloat162float(h0));
            pl.y = __float2bfloat16(v1 - __bfloat162float(h1));
            size_t off = ((size_t)(b * SS + row)) * EE + h * DD + d;
            *(__nv_bfloat162*)(g_Chi + off) = ph;
            *(__nv_bfloat162*)(g_Clo + off) = pl;
        }
    }
}

// ---------------- launch ----------------
extern "C" void kernel_launch(void* const* d_in, const int* in_sizes, int n_in,
                              void* d_out, int out_size)
{
    const float* q    = (const float*)d_in[0];
    const float* k    = (const float*)d_in[1];
    const float* v    = (const float*)d_in[2];
    const int*   mask = (const int*)  d_in[3];
    const float* Wqkv = (const float*)d_in[4];
    const float* bqkv = (const float*)d_in[5];
    const float* Wout = (const float*)d_in[6];
    const float* bout = (const float*)d_in[7];
    float* out = (float*)d_out;

    cudaFuncSetAttribute(mma_gemm<0>, cudaFuncAttributeMaxDynamicSharedMemorySize, GEMM_SMEM);
    cudaFuncSetAttribute(mma_gemm<1>, cudaFuncAttributeMaxDynamicSharedMemorySize, GEMM_SMEM);
    cudaFuncSetAttribute(attn_mma,    cudaFuncAttributeMaxDynamicSharedMemorySize, ATTN_SMEM);

    __nv_bfloat16 *Ahi, *Alo, *Whi, *Wlo, *Chi, *Clo;
    cudaGetSymbolAddress((void**)&Ahi, g_Ahi);
    cudaGetSymbolAddress((void**)&Alo, g_Alo);
    cudaGetSymbolAddress((void**)&Whi, g_Whi);
    cudaGetSymbolAddress((void**)&Wlo, g_Wlo);
    cudaGetSymbolAddress((void**)&Chi, g_Chi);
    cudaGetSymbolAddress((void**)&Clo, g_Clo);

    const int n4 = MT * EE / 4;
    conv_rows3<<<dim3(n4 / 256, 3), 256>>>(q, k, v, Ahi, Alo);

    conv_wT<<<dim3(3 * EE / 32, EE / 32), 256>>>(Wqkv, 3 * EE, Whi, Wlo);
    conv_wT<<<dim3(EE / 32, EE / 32), 256>>>(Wout, EE, Whi + (size_t)3 * EE * EE, Wlo + (size_t)3 * EE * EE);

    mask_bits<<<SS * (SS / 32) / 8, 256>>>(mask);

    mma_gemm<0><<<dim3(EE / 128, MT / 128, 3), 256, GEMM_SMEM>>>(Ahi, Alo, bqkv, nullptr);

    attn_mma<<<dim3(SS / AQ, HH, BB), 256, ATTN_SMEM>>>();

    mma_gemm<1><<<dim3(EE / 128, MT / 128, 1), 256, GEMM_SMEM>>>(Chi, Clo, bout, out);
}